// round 14
// baseline (speedup 1.0000x reference)
#include <cuda_runtime.h>
#include <cuda_fp16.h>

#define BATCH  64
#define SEQ    256
#define EMBED  512
#define HIDDEN 1024
#define G4     4096
#define BT     (BATCH * SEQ)
#define NCTA   128

// ---------------- scratch ----------------
// packed h (fp16): per t, uint4 entries [(ks*4 + mg)*32 + lane], 8 halves each
__device__ __align__(256) float  g_pre [(size_t)BT * G4];
__device__ __align__(256) __half g_hpk [(size_t)(SEQ + 1) * 65536];
__device__ __align__(256) float  g_hist[(size_t)BT * HIDDEN];
__device__ unsigned g_sync;

// ---------------- fp16 helpers ----------------
__device__ __forceinline__ unsigned pkh2(float lo, float hi) {
    __half2 h = __floats2half2_rn(lo, hi);
    return *(unsigned*)&h;
}
__device__ __forceinline__ void mma16(float* c, unsigned a0, unsigned a1,
                                      unsigned a2, unsigned a3,
                                      unsigned b0, unsigned b1) {
    asm volatile(
        "mma.sync.aligned.m16n8k16.row.col.f32.f16.f16.f32 "
        "{%0,%1,%2,%3},{%4,%5,%6,%7},{%8,%9},{%0,%1,%2,%3};"
        : "+f"(c[0]), "+f"(c[1]), "+f"(c[2]), "+f"(c[3])
        : "r"(a0), "r"(a1), "r"(a2), "r"(a3), "r"(b0), "r"(b1));
}

// ---------------------------------------------------------------------------
// fp16 GEMM: C[M,N] = A[M,K] @ B[N,K]^T (+bias1+bias2), fp32 accum.
// Block 128x128x32, 8 warps as 2(m) x 4(n), warp tile 64x32, m16n8k16.
// perm: 0 none; 1: out_row=(m&255)*64+(m>>8); 2: out_row=(m&63)*256+(m>>6).
// ---------------------------------------------------------------------------
__global__ __launch_bounds__(256, 2) void gemm_f16(
    const float* __restrict__ A, int lda,
    const float* __restrict__ B, int ldb,
    float* __restrict__ C, int ldc, int K,
    const float* __restrict__ bias1, const float* __restrict__ bias2,
    int perm)
{
    __shared__ unsigned As[128][20];
    __shared__ unsigned Bs[128][20];
    const int tid = threadIdx.x, w = tid >> 5, lane = tid & 31;
    const int g = lane >> 2, cq = lane & 3;
    const int wm = w >> 2;
    const int wn = w & 3;
    const long m0 = (long)blockIdx.x * 128, n0 = (long)blockIdx.y * 128;

    float acc[4][4][4];
#pragma unroll
    for (int mi = 0; mi < 4; mi++)
#pragma unroll
        for (int ni = 0; ni < 4; ni++)
#pragma unroll
            for (int e = 0; e < 4; e++) acc[mi][ni][e] = 0.f;

    const int srow = tid >> 3, scol = (tid & 7) * 4;

    for (int k0 = 0; k0 < K; k0 += 32) {
#pragma unroll
        for (int p = 0; p < 4; p++) {
            int r = p * 32 + srow;
            float4 v = *(const float4*)(A + (size_t)(m0 + r) * lda + k0 + scol);
            *(uint2*)&As[r][scol >> 1] =
                make_uint2(pkh2(v.x, v.y), pkh2(v.z, v.w));
        }
#pragma unroll
        for (int p = 0; p < 4; p++) {
            int r = p * 32 + srow;
            float4 v = *(const float4*)(B + (size_t)(n0 + r) * ldb + k0 + scol);
            *(uint2*)&Bs[r][scol >> 1] =
                make_uint2(pkh2(v.x, v.y), pkh2(v.z, v.w));
        }
        __syncthreads();
#pragma unroll
        for (int kk2 = 0; kk2 < 2; kk2++) {
            const int off = kk2 * 8;
            unsigned a[4][4], b[4][2];
#pragma unroll
            for (int mi = 0; mi < 4; mi++) {
                int rb = wm * 64 + mi * 16 + g;
                a[mi][0] = As[rb][off + cq];
                a[mi][1] = As[rb + 8][off + cq];
                a[mi][2] = As[rb][off + cq + 4];
                a[mi][3] = As[rb + 8][off + cq + 4];
            }
#pragma unroll
            for (int ni = 0; ni < 4; ni++) {
                int nb = wn * 32 + ni * 8 + g;
                b[ni][0] = Bs[nb][off + cq];
                b[ni][1] = Bs[nb][off + cq + 4];
            }
#pragma unroll
            for (int mi = 0; mi < 4; mi++)
#pragma unroll
                for (int ni = 0; ni < 4; ni++)
                    mma16(acc[mi][ni], a[mi][0], a[mi][1], a[mi][2], a[mi][3],
                          b[ni][0], b[ni][1]);
        }
        __syncthreads();
    }

#pragma unroll
    for (int ni = 0; ni < 4; ni++) {
        long col = n0 + wn * 32 + ni * 8 + 2 * cq;
        float bv0 = 0.f, bv1 = 0.f;
        if (bias1) { bv0 += bias1[col]; bv1 += bias1[col + 1]; }
        if (bias2) { bv0 += bias2[col]; bv1 += bias2[col + 1]; }
#pragma unroll
        for (int mi = 0; mi < 4; mi++) {
            long r0 = m0 + wm * 64 + mi * 16 + g;
            long r1 = r0 + 8;
            long p0 = (perm == 1) ? (r0 & 255) * 64 + (r0 >> 8)
                    : (perm == 2) ? (r0 & 63) * 256 + (r0 >> 6) : r0;
            long p1 = (perm == 1) ? (r1 & 255) * 64 + (r1 >> 8)
                    : (perm == 2) ? (r1 & 63) * 256 + (r1 >> 6) : r1;
            *(float2*)(C + p0 * ldc + col) =
                make_float2(acc[mi][ni][0] + bv0, acc[mi][ni][1] + bv1);
            *(float2*)(C + p1 * ldc + col) =
                make_float2(acc[mi][ni][2] + bv0, acc[mi][ni][3] + bv1);
        }
    }
}

// ---------------------------------------------------------------------------
__global__ void init_kernel()
{
    int idx = blockIdx.x * blockDim.x + threadIdx.x;   // 65536 threads
    g_hpk[idx] = __ushort_as_half((unsigned short)0);  // h_0 packed block = 0
    if (idx == 0) g_sync = 0;
}

// ---------------------------------------------------------------------------
// Persistent LSTM recurrence (fp16 operands, fp32 accum), TMA-multicast h.
// 128 CTAs = 32 clusters(4), 1 CTA/SM. CTA j owns units [8j,8j+8) -> 32 gate
// rows. Warps: 2 m-halves x 4 K-splits. Per step: each cluster rank r
// bulk-copies h K-slice r (32 KB) and multicasts it to all 4 peers' smem
// (chip L2 h traffic 4 MB/step, was 16); warp kh waits slice-kh mbarrier,
// mma from smem (A LDS.128 + W LDS.64, both conflict-free); K-partials
// reduced in smem; fused cell (c in registers); red.release/ld.acquire
// grid barrier sequences steps and provides WAR safety for the multicast.
// ---------------------------------------------------------------------------
#define P_STRIDE 34
#define A_OFF    65536                              // 64 KB W | 128 KB A
#define P_OFF2   (A_OFF + 131072)                   // 34816 B partials
#define MBAR_OFF (P_OFF2 + 4 * 64 * P_STRIDE * 4)   // 4 mbarriers
#define SMB      (MBAR_OFF + 64)                    // 231488 B  (cap 232448)
#define WP_UINT2 8192

__global__ __launch_bounds__(256, 1) __cluster_dims__(4, 1, 1)
void lstm_persistent(const float* __restrict__ pre, const float* __restrict__ Whh)
{
    extern __shared__ unsigned char smraw[];
    uint2* Wp2 = (uint2*)smraw;                     // B-frags [(ks*4+ni)*32+lane]
    float* P   = (float*)(smraw + P_OFF2);          // partials [4][64][34]

    const int j = blockIdx.x, tid = threadIdx.x;
    const int w = tid >> 5, lane = tid & 31;
    const int g = lane >> 2, cq = lane & 3;

    unsigned smem_base;
    asm("{ .reg .u64 t; cvta.to.shared.u64 t, %1; cvt.u32.u64 %0, t; }"
        : "=r"(smem_base) : "l"(smraw));
    unsigned rank;
    asm("mov.u32 %0, %%cluster_ctarank;" : "=r"(rank));

    // ---- one-time: pack W_hh rows (gate-grouped) into fp16 B-fragments ----
    for (int idx = tid; idx < WP_UINT2; idx += 256) {
        int l  = idx & 31;
        int ni = (idx >> 5) & 3;
        int ks = idx >> 7;                          // 0..63
        int g2 = l >> 2, c2 = l & 3;
        const float* wr = Whh + (size_t)(ni * 1024 + 8 * j + g2) * 1024 +
                          ks * 16 + 2 * c2;
        Wp2[idx] = make_uint2(pkh2(wr[0], wr[1]), pkh2(wr[8], wr[9]));
    }
    // mbarriers: one per K-slice, arrive count 1 (the expect_tx arriver)
    if (tid == 0) {
#pragma unroll
        for (int r = 0; r < 4; r++)
            asm volatile("mbarrier.init.shared.b64 [%0], %1;"
                         :: "r"(smem_base + MBAR_OFF + r * 8), "r"(1u) : "memory");
    }
    __syncthreads();
    // peers' mbarriers must be live before any multicast targets them
    asm volatile("barrier.cluster.arrive.aligned;" ::: "memory");
    asm volatile("barrier.cluster.wait.aligned;" ::: "memory");

    const int mtw = w & 1;        // m-half: rows [mtw*32, +32)
    const int kh  = w >> 1;       // K-split: ks range [kh*16, +16)  == slice kh

    const int b0 = tid >> 3, u0 = tid & 7;
    const int b1 = (tid + 256) >> 3;
    float c0 = 0.f, c1 = 0.f;     // cell state in registers

    unsigned* syncp = &g_sync;
    const uint4* Asm = (const uint4*)(smraw + A_OFF);

    for (int t = 0; t < SEQ; t++) {
        // issue this rank's h K-slice, multicast to the whole cluster
        if (tid == 0) {
            asm volatile("fence.proxy.async.shared::cta;" ::: "memory");
#pragma unroll
            for (int r = 0; r < 4; r++)
                asm volatile("mbarrier.arrive.expect_tx.shared.b64 _, [%0], %1;"
                             :: "r"(smem_base + MBAR_OFF + r * 8), "r"(32768u)
                             : "memory");
            const char* src = (const char*)g_hpk +
                              (size_t)t * 131072 + (size_t)rank * 32768;
            asm volatile(
                "cp.async.bulk.shared::cluster.global"
                ".mbarrier::complete_tx::bytes.multicast::cluster "
                "[%0], [%1], %2, [%3], %4;"
                :: "r"(smem_base + A_OFF + rank * 32768), "l"(src), "r"(32768u),
                   "r"(smem_base + MBAR_OFF + rank * 8),
                   "h"((unsigned short)0xF)
                : "memory");
        }

        // pre-gate prefetch (independent of TMA/mma)
        const float* pp0 = pre + ((size_t)t * 64 + b0) * G4 + 8 * j + u0;
        const float* pp1 = pre + ((size_t)t * 64 + b1) * G4 + 8 * j + u0;
        float p0i = pp0[0], p0f = pp0[1024], p0g = pp0[2048], p0o = pp0[3072];
        float p1i = pp1[0], p1f = pp1[1024], p1g = pp1[2048], p1o = pp1[3072];

        // wait for this warp's K-slice
        {
            unsigned mb = smem_base + MBAR_OFF + kh * 8;
            unsigned par = (unsigned)(t & 1), done;
            do {
                asm volatile(
                    "{\n\t.reg .pred p;\n\t"
                    "mbarrier.try_wait.parity.acquire.cta.shared::cta.b64 "
                    "p, [%1], %2;\n\t"
                    "selp.b32 %0, 1, 0, p;\n\t}"
                    : "=r"(done) : "r"(mb), "r"(par) : "memory");
            } while (!done);
        }

        float acc[2][4][4];
#pragma unroll
        for (int mi = 0; mi < 2; mi++)
#pragma unroll
            for (int ni = 0; ni < 4; ni++)
#pragma unroll
                for (int e = 0; e < 4; e++) acc[mi][ni][e] = 0.f;

#pragma unroll 4
        for (int ksl = 0; ksl < 16; ksl++) {
            int ks = kh * 16 + ksl;
            uint4 a0 = Asm[(ks * 4 + mtw * 2 + 0) * 32 + lane];
            uint4 a1 = Asm[(ks * 4 + mtw * 2 + 1) * 32 + lane];
            uint2 bf[4];
#pragma unroll
            for (int ni = 0; ni < 4; ni++)
                bf[ni] = Wp2[(ks * 4 + ni) * 32 + lane];
#pragma unroll
            for (int ni = 0; ni < 4; ni++) {
                mma16(acc[0][ni], a0.x, a0.y, a0.z, a0.w, bf[ni].x, bf[ni].y);
                mma16(acc[1][ni], a1.x, a1.y, a1.z, a1.w, bf[ni].x, bf[ni].y);
            }
        }

        // partials -> smem
#pragma unroll
        for (int mi = 0; mi < 2; mi++) {
            int r0 = mtw * 32 + mi * 16 + g;
#pragma unroll
            for (int ni = 0; ni < 4; ni++) {
                int col = ni * 8 + 2 * cq;
                *(float2*)&P[(kh * 64 + r0) * P_STRIDE + col] =
                    make_float2(acc[mi][ni][0], acc[mi][ni][1]);
                *(float2*)&P[(kh * 64 + r0 + 8) * P_STRIDE + col] =
                    make_float2(acc[mi][ni][2], acc[mi][ni][3]);
            }
        }
        __syncthreads();

        // fused cell update (2 units per thread, c in registers)
#pragma unroll
        for (int q = 0; q < 2; q++) {
            int b = q ? b1 : b0;
            float gi = q ? p1i : p0i, gf = q ? p1f : p0f;
            float gg = q ? p1g : p0g, go = q ? p1o : p0o;
#pragma unroll
            for (int kk = 0; kk < 4; kk++) {
                const float* pr = &P[(kk * 64 + b) * P_STRIDE];
                gi += pr[u0]; gf += pr[8 + u0];
                gg += pr[16 + u0]; go += pr[24 + u0];
            }
            float cc = q ? c1 : c0;
            float iv = 1.f / (1.f + __expf(-gi));
            float fv = 1.f / (1.f + __expf(-gf));
            float gv = tanhf(gg);
            float ov = 1.f / (1.f + __expf(-go));
            cc = fv * cc + iv * gv;
            if (q) c1 = cc; else c0 = cc;
            float hv = ov * tanhf(cc);

            // packed fp16 h write for next step's A-fragments
            int ug = 8 * j + u0;
            int ks = ug >> 4, kk16 = ug & 15, mg = b >> 4;
            int ln = (b & 7) * 4 + ((kk16 & 7) >> 1);
            int hf = ((b >> 3) & 1) * 2 + ((kk16 >> 3) & 1) * 4 + (kk16 & 1);
            g_hpk[(size_t)(t + 1) * 65536 +
                  (((size_t)ks * 4 + mg) * 32 + ln) * 8 + hf] =
                __float2half_rn(hv);
            // full-precision h for the fc GEMM
            g_hist[((size_t)t * 64 + b) * 1024 + ug] = hv;
        }

        // grid barrier: red.release arrive + ld.acquire poll
        __syncthreads();
        if (tid == 0) {
            asm volatile("red.release.gpu.global.add.u32 [%0], 1;"
                         :: "l"(syncp) : "memory");
            const unsigned target = (unsigned)NCTA * (unsigned)(t + 1);
            unsigned v;
            do {
                asm volatile("ld.acquire.gpu.global.u32 %0, [%1];"
                             : "=r"(v) : "l"(syncp) : "memory");
            } while (v < target);
        }
        __syncthreads();
    }
}

// ---------------------------------------------------------------------------
extern "C" void kernel_launch(void* const* d_in, const int* in_sizes, int n_in,
                              void* d_out, int out_size)
{
    const float* emb  = (const float*)d_in[0];
    const float* W_ih = (const float*)d_in[1];
    const float* W_hh = (const float*)d_in[2];
    const float* b_ih = (const float*)d_in[3];
    const float* b_hh = (const float*)d_in[4];
    const float* W_fc = (const float*)d_in[5];
    const float* b_fc = (const float*)d_in[6];
    float* out = (float*)d_out;

    float *pre, *hist;
    cudaGetSymbolAddress((void**)&pre,  g_pre);
    cudaGetSymbolAddress((void**)&hist, g_hist);

    init_kernel<<<64, 1024>>>();

    // prepass: pre[t*64+b] = emb[b*256+t] @ W_ih^T + b_ih + b_hh   (perm=1)
    gemm_f16<<<dim3(BT / 128, G4 / 128), 256>>>(
        emb, EMBED, W_ih, EMBED, pre, G4, EMBED, b_ih, b_hh, 1);

    cudaFuncSetAttribute(lstm_persistent,
                         cudaFuncAttributeMaxDynamicSharedMemorySize, SMB);
    lstm_persistent<<<NCTA, 256, SMB>>>(pre, W_hh);

    // fc: out[b*256+t] = hist[t*64+b] @ W_fc^T + b_fc   (perm=2)
    gemm_f16<<<dim3(BT / 128, HIDDEN / 128), 256>>>(
        hist, HIDDEN, W_fc, HIDDEN, out, HIDDEN, HIDDEN, b_fc, nullptr, 2);
}